// round 9
// baseline (speedup 1.0000x reference)
#include <cuda_runtime.h>

// out[b,c,h,w] = x[b,c,h,w] * (h%3 != 0) * (w%3 != 0)
//
// Unfold(k=2,stride=3,dil=2,pad=1)+fold(identical geometry) == elementwise 0/1
// coverage mask, separable in h,w. Rows h%3==0 are all-zero in the output.
//
// R9 = R8 split-stream winner, refined:
//  - ZERO blocks first: pure 256-bit stores of zero (no loads, no waits) —
//    drain write BW from cycle 0.
//  - LIVE blocks: unconditional LDG.128 x4 (plane-strided, MLP=4), masked
//    multiply, evict-first streaming stores (__stcs) so the never-re-read
//    output doesn't evict the 88 MB read set from L2.
//
// Geometry: 32768 planes of 32x32 f32; plane = 256 float4; row = 8 float4 =
// one 128B line. Live rows/plane: 21 (h = 3k/2+1). Zero rows/plane: 11 (h=3k).

static constexpr int THREADS     = 256;
static constexpr int PLANES      = 64 * 512;                    // 32768
static constexpr int PQ          = PLANES / 4;                  // 8192
static constexpr int LIVE_F4     = PQ * 21 * 8;                 // 1,376,256
static constexpr int ZERO_F8     = PLANES * 11 * 4;             // 1,441,792 (8-float units)
static constexpr int LIVE_BLOCKS = LIVE_F4 / THREADS;           // 5376
static constexpr int ZERO_BLOCKS = ZERO_F8 / THREADS;           // 5632

__device__ __forceinline__ void stg256_zero(float* p) {
    asm volatile(
        "st.global.v8.f32 [%0], {%1,%1,%1,%1,%1,%1,%1,%1};"
        :: "l"(p), "f"(0.0f) : "memory");
}

__global__ void __launch_bounds__(THREADS)
unfoldfold_split_kernel(const float4* __restrict__ x,
                        float4* __restrict__ out) {
    int b = blockIdx.x;

    if (b < ZERO_BLOCKS) {
        // ---- zero rows: pure 256-bit stores, no loads ----
        int t = b * THREADS + threadIdx.x;       // [0, ZERO_F8)
        int c = t & 3;                           // float8 within row (4 per row)
        int r = t >> 2;                          // zero-row serial
        int k = r % 11;                          // zero-row index within plane
        int p = r / 11;
        int h = 3 * k;                           // 0,3,...,30

        float* dst = (float*)out + (size_t)p * 1024 + h * 32 + c * 8;
        stg256_zero(dst);
    } else {
        // ---- live rows: read, mask by w, streaming store ----
        int t = (b - ZERO_BLOCKS) * THREADS + threadIdx.x;  // [0, LIVE_F4)
        int c  = t & 7;                          // float4 column within row
        int r  = t >> 3;                         // live-row serial
        int k  = r % 21;                         // live-row index within plane
        int p0 = r / 21;                         // plane within first chunk
        int h  = (3 * k) / 2 + 1;                // 1,2,4,5,7,8,...,31

        int w0 = c << 2;
        float m0 = (float)(((w0 + 0) % 3) != 0);
        float m1 = (float)(((w0 + 1) % 3) != 0);
        float m2 = (float)(((w0 + 2) % 3) != 0);
        float m3 = (float)(((w0 + 3) % 3) != 0);

        int base = h * 8 + c;
        int i0 = (p0         ) * 256 + base;
        int i1 = (p0 +     PQ) * 256 + base;
        int i2 = (p0 + 2 * PQ) * 256 + base;
        int i3 = (p0 + 3 * PQ) * 256 + base;

        float4 v0 = x[i0];
        float4 v1 = x[i1];
        float4 v2 = x[i2];
        float4 v3 = x[i3];

        v0.x *= m0; v0.y *= m1; v0.z *= m2; v0.w *= m3;
        v1.x *= m0; v1.y *= m1; v1.z *= m2; v1.w *= m3;
        v2.x *= m0; v2.y *= m1; v2.z *= m2; v2.w *= m3;
        v3.x *= m0; v3.y *= m1; v3.z *= m2; v3.w *= m3;

        __stcs(&out[i0], v0);
        __stcs(&out[i1], v1);
        __stcs(&out[i2], v2);
        __stcs(&out[i3], v3);
    }
}

extern "C" void kernel_launch(void* const* d_in, const int* in_sizes, int n_in,
                              void* d_out, int out_size) {
    const float4* x = (const float4*)d_in[0];
    float4* out     = (float4*)d_out;

    unfoldfold_split_kernel<<<ZERO_BLOCKS + LIVE_BLOCKS, THREADS>>>(x, out);
}

// round 10
// speedup vs baseline: 1.0514x; 1.0514x over previous
#include <cuda_runtime.h>

// out[b,c,h,w] = x[b,c,h,w] * (h%3 != 0) * (w%3 != 0)
//
// Unfold(k=2,stride=3,dil=2,pad=1)+fold(identical geometry) == elementwise 0/1
// coverage mask, separable in h,w. Rows h%3==0 are all-zero in the output.
//
// R10 = R8 (proven: ncu 27.3us, DRAM 75.3%) with exactly ONE change:
// zero path uses 256-bit stores (st.global.v8.f32), halving zero-block count.
// Live blocks FIRST (reads start at cycle 0), plain stores everywhere else.
//
// Geometry: 32768 planes of 32x32 f32; plane = 256 float4; row = 8 float4 =
// one 128B line. Live rows/plane: 21 (h = 3k/2+1). Zero rows/plane: 11 (h=3k).

static constexpr int THREADS     = 256;
static constexpr int PLANES      = 64 * 512;                    // 32768
static constexpr int PQ          = PLANES / 4;                  // 8192
static constexpr int LIVE_F4     = PQ * 21 * 8;                 // 1,376,256
static constexpr int ZERO_F8     = PLANES * 11 * 4;             // 1,441,792
static constexpr int LIVE_BLOCKS = LIVE_F4 / THREADS;           // 5376
static constexpr int ZERO_BLOCKS = ZERO_F8 / THREADS;           // 5632

__device__ __forceinline__ void stg256_zero(float* p) {
    asm volatile(
        "st.global.v8.f32 [%0], {%1,%1,%1,%1,%1,%1,%1,%1};"
        :: "l"(p), "f"(0.0f) : "memory");
}

__global__ void __launch_bounds__(THREADS)
unfoldfold_split_kernel(const float4* __restrict__ x,
                        float4* __restrict__ out) {
    int b = blockIdx.x;

    if (b < LIVE_BLOCKS) {
        // ---- live rows: read, mask by w, write (identical to R8) ----
        int t = b * THREADS + threadIdx.x;       // [0, LIVE_F4)
        int c  = t & 7;                          // float4 column within row
        int r  = t >> 3;                         // live-row serial
        int k  = r % 21;                         // live-row index within plane
        int p0 = r / 21;                         // plane within first chunk
        int h  = (3 * k) / 2 + 1;                // 1,2,4,5,7,8,...,31

        int w0 = c << 2;
        float m0 = (float)(((w0 + 0) % 3) != 0);
        float m1 = (float)(((w0 + 1) % 3) != 0);
        float m2 = (float)(((w0 + 2) % 3) != 0);
        float m3 = (float)(((w0 + 3) % 3) != 0);

        int base = h * 8 + c;
        int i0 = (p0         ) * 256 + base;
        int i1 = (p0 +     PQ) * 256 + base;
        int i2 = (p0 + 2 * PQ) * 256 + base;
        int i3 = (p0 + 3 * PQ) * 256 + base;

        // Unconditional, batched loads (MLP = 4)
        float4 v0 = x[i0];
        float4 v1 = x[i1];
        float4 v2 = x[i2];
        float4 v3 = x[i3];

        v0.x *= m0; v0.y *= m1; v0.z *= m2; v0.w *= m3;
        v1.x *= m0; v1.y *= m1; v1.z *= m2; v1.w *= m3;
        v2.x *= m0; v2.y *= m1; v2.z *= m2; v2.w *= m3;
        v3.x *= m0; v3.y *= m1; v3.z *= m2; v3.w *= m3;

        out[i0] = v0;
        out[i1] = v1;
        out[i2] = v2;
        out[i3] = v3;
    } else {
        // ---- zero rows: pure 256-bit stores, no loads, no waits ----
        int t = (b - LIVE_BLOCKS) * THREADS + threadIdx.x;   // [0, ZERO_F8)
        int c = t & 3;                           // float8 within row (4 per row)
        int r = t >> 2;                          // zero-row serial
        int k = r % 11;                          // zero-row index within plane
        int p = r / 11;
        int h = 3 * k;                           // 0,3,...,30

        float* dst = (float*)out + (size_t)p * 1024 + h * 32 + c * 8;
        stg256_zero(dst);
    }
}

extern "C" void kernel_launch(void* const* d_in, const int* in_sizes, int n_in,
                              void* d_out, int out_size) {
    const float4* x = (const float4*)d_in[0];
    float4* out     = (float4*)d_out;

    unfoldfold_split_kernel<<<LIVE_BLOCKS + ZERO_BLOCKS, THREADS>>>(x, out);
}